// round 10
// baseline (speedup 1.0000x reference)
#include <cuda_runtime.h>

// Problem constants
#define D        64
#define S        64
#define BSZ      512
#define LTW      2016          // d*(d-1)/2
#define ZROW     6112          // lt + d*d
#define OUT_ELEMS (BSZ * S * D) // 2097152, z_adj follows at this offset

typedef unsigned long long u64;
typedef ulonglong2 u64x2;

// ---------------- f32x2 packed-math helpers (sm_100+) ----------------
__device__ __forceinline__ u64 pack2(float lo, float hi) {
    u64 r; asm("mov.b64 %0, {%1,%2};" : "=l"(r) : "f"(lo), "f"(hi)); return r;
}
__device__ __forceinline__ void unpack2(u64 v, float& lo, float& hi) {
    asm("mov.b64 {%0,%1}, %2;" : "=f"(lo), "=f"(hi) : "l"(v));
}
__device__ __forceinline__ u64 fma2(u64 a, u64 b, u64 c) {
    u64 d; asm("fma.rn.f32x2 %0, %1, %2, %3;" : "=l"(d) : "l"(a), "l"(b), "l"(c)); return d;
}
__device__ __forceinline__ u64 relu2(u64 v) {
    float lo, hi; unpack2(v, lo, hi);
    lo = fmaxf(lo, 0.0f); hi = fmaxf(hi, 0.0f);
    return pack2(lo, hi);
}

// Packed-transposed x: xT2[i*256 + p] = (x[2p][i], x[2p+1][i])
__device__ u64 xT2g[64 * 256];

// ---------------- Kernel A: z_adj[s] = z_p^T @ z_lt @ z_p ----------------
__global__ void zadj_kernel(const float* __restrict__ z, float* __restrict__ adj_out) {
    extern __shared__ float sm[];
    float* lt  = sm;           // 4096
    float* p   = sm + 4096;    // 4096
    float* tmp = sm + 8192;    // 4096
    const int s   = blockIdx.x;
    const int tid = threadIdx.x;
    const int nt  = blockDim.x;
    const float* zs = z + s * ZROW;

    for (int e = tid; e < 4096; e += nt) {
        lt[e] = 0.0f;
        p[e]  = zs[LTW + e];
    }
    __syncthreads();

    for (int k = tid; k < LTW; k += nt) {
        int i = (int)((sqrtf(8.0f * (float)k + 1.0f) + 1.0f) * 0.5f);
        while (i * (i - 1) / 2 > k)       --i;
        while ((i + 1) * i / 2 <= k)      ++i;
        int j = k - i * (i - 1) / 2;
        lt[i * 64 + j] = zs[k];
    }
    __syncthreads();

    for (int e = tid; e < 4096; e += nt) {
        int r = e >> 6, j = e & 63;
        float acc = 0.0f;
        for (int t = 0; t < r; ++t)
            acc += lt[r * 64 + t] * p[t * 64 + j];
        tmp[e] = acc;
    }
    __syncthreads();

    for (int e = tid; e < 4096; e += nt) {
        int i = e >> 6, j = e & 63;
        float acc = 0.0f;
        #pragma unroll 8
        for (int r = 0; r < 64; ++r)
            acc += p[r * 64 + i] * tmp[r * 64 + j];
        adj_out[s * 4096 + e] = acc;
    }
}

// ---------------- Kernel A2: pack/transpose x into xT2g ----------------
__global__ void xpack_kernel(const float* __restrict__ x) {
    int idx = blockIdx.x * 256 + threadIdx.x;   // 0 .. 32767
    float v = x[idx];
    int b = idx >> 6, i = idx & 63;
    ((float*)xT2g)[(i * 256 + (b >> 1)) * 2 + (b & 1)] = v;
}

// ---------------- Kernel B: fused 4-layer channel MLP ----------------
// Grid (c=64, s=64); 128 threads; thread = 4 batches (2 f32x2 pairs p0=tid, p1=tid+128).
// Layer 0 shares each weight LDS.128 across both pairs (1 LDS : 4 FFMA2), computed in
// two 16-output halves to bound register pressure; pair1 parked in shared.
//
// Dynamic shared layout (float index):
//   wzd   [4096]  @ 0       wz dup: [(i*32+o)*2]
//   w1d   [2048]  @ 4096
//   w2d   [2048]  @ 6144
//   w3d   [64]    @ 8192
//   b0d   [64]    @ 8256;  b1d @ 8320; b2d @ 8384; b3d[2] @ 8448
//   zcs   [64]    @ 8452
//   park  [4096 u64 = 8192 f] @ 8520   (aliased as wtmp[32*65] during staging)
#define WZ_OFF   0
#define W1_OFF   4096
#define W2_OFF   6144
#define W3_OFF   8192
#define B0_OFF   8256
#define B1_OFF   8320
#define B2_OFF   8384
#define B3_OFF   8448
#define ZC_OFF   8452
#define PK_OFF   8520
#define SMEM_FLOATS (PK_OFF + 8192)
#define SMEM_BYTES  (SMEM_FLOATS * 4)

__global__ void __launch_bounds__(128, 2) mlp_kernel(
    const float* __restrict__ adj,
    const float* __restrict__ W0, const float* __restrict__ b0,
    const float* __restrict__ W1, const float* __restrict__ b1,
    const float* __restrict__ W2, const float* __restrict__ b2,
    const float* __restrict__ W3, const float* __restrict__ b3,
    float* __restrict__ out)
{
    extern __shared__ __align__(16) float sm[];
    float* wzd = sm + WZ_OFF;
    float* w1d = sm + W1_OFF;
    float* w2d = sm + W2_OFF;
    float* w3d = sm + W3_OFF;
    float* b0d = sm + B0_OFF;
    float* b1d = sm + B1_OFF;
    float* b2d = sm + B2_OFF;
    float* b3d = sm + B3_OFF;
    float* zcs = sm + ZC_OFF;
    u64*   park = (u64*)(sm + PK_OFF);
    float* wtmp = sm + PK_OFF;          // staging alias (32*65 = 2080 floats)

    const int c = blockIdx.x;
    const int s = blockIdx.y;
    const int tid = threadIdx.x;

    // ---- phase 1: stage weights/biases ----
    if (tid < 64) zcs[tid] = adj[s * 4096 + tid * 64 + c];
    for (int e = tid; e < 1024; e += 128) {
        float w = W1[c * 1024 + e]; w1d[2 * e] = w; w1d[2 * e + 1] = w;
        float v = W2[c * 1024 + e]; w2d[2 * e] = v; w2d[2 * e + 1] = v;
    }
    for (int e = tid; e < 2048; e += 128) {
        int o = e >> 6, i = e & 63;
        wtmp[o * 65 + i] = W0[c * 2048 + e];
    }
    if (tid < 32) {
        float w = W3[c * 32 + tid]; w3d[2 * tid] = w; w3d[2 * tid + 1] = w;
        float q = b0[c * 32 + tid]; b0d[2 * tid] = q; b0d[2 * tid + 1] = q;
        q = b1[c * 32 + tid]; b1d[2 * tid] = q; b1d[2 * tid + 1] = q;
        q = b2[c * 32 + tid]; b2d[2 * tid] = q; b2d[2 * tid + 1] = q;
    }
    if (tid == 0) { float q = b3[c]; b3d[0] = q; b3d[1] = q; }
    __syncthreads();

    // ---- phase 2: wz[i][o] = W0[c][o][i] * zc[i], lane-duplicated ----
    for (int e = tid; e < 2048; e += 128) {
        int o = e & 31, i = e >> 5;
        float w = wtmp[o * 65 + i] * zcs[i];
        ((u64*)wzd)[i * 32 + o] = pack2(w, w);
    }
    __syncthreads();   // also fences wtmp -> park reuse

    const u64x2* wz2 = (const u64x2*)wzd;   // [i*16 + oq]
    const u64x2* w1q = (const u64x2*)w1d;   // [o*16 + iq]
    const u64x2* w2q = (const u64x2*)w2d;
    const u64x2* w3q = (const u64x2*)w3d;   // [iq]
    const u64* b0q = (const u64*)b0d;
    const u64* b1q = (const u64*)b1d;
    const u64* b2q = (const u64*)b2d;
    const u64* b3q = (const u64*)b3d;

    const u64* __restrict__ xp0 = xT2g + tid;         // pair p0 = tid
    const u64* __restrict__ xp1 = xT2g + tid + 128;   // pair p1 = tid + 128

    // ---- layer 0 for BOTH pairs, in two 16-output halves ----
    // pair0 half results retained in regs (a0), pair1 halves parked in shared.
    u64 a0[32];
    #pragma unroll 1
    for (int h = 0; h < 2; ++h) {
        u64 c0[16], c1[16];
        #pragma unroll
        for (int o = 0; o < 16; ++o) { c0[o] = b0q[h * 16 + o]; c1[o] = c0[o]; }

        #pragma unroll 4
        for (int i = 0; i < 64; ++i) {
            u64 xa = xp0[i * 256];
            u64 xb = xp1[i * 256];
            const u64x2* wrow = wz2 + i * 16 + h * 8;
            #pragma unroll
            for (int oq = 0; oq < 8; ++oq) {
                u64x2 w = wrow[oq];                   // LDS.128 shared by 4 batches
                c0[2 * oq]     = fma2(w.x, xa, c0[2 * oq]);
                c1[2 * oq]     = fma2(w.x, xb, c1[2 * oq]);
                c0[2 * oq + 1] = fma2(w.y, xa, c0[2 * oq + 1]);
                c1[2 * oq + 1] = fma2(w.y, xb, c1[2 * oq + 1]);
            }
        }
        #pragma unroll
        for (int o = 0; o < 16; ++o) {
            a0[h * 16 + o] = relu2(c0[o]);
            park[(h * 16 + o) * 128 + tid] = relu2(c1[o]);
        }
    }

    const int base = s * 64 + c;

    // ---- layers 1-3 per pair (unroll 1 keeps one pair's regs live) ----
    #pragma unroll 1
    for (int kp = 0; kp < 2; ++kp) {
        u64 a[32];
        if (kp == 0) {
            #pragma unroll
            for (int o = 0; o < 32; ++o) a[o] = a0[o];
        } else {
            #pragma unroll
            for (int o = 0; o < 32; ++o) a[o] = park[o * 128 + tid];
        }

        // layer 1: 32 -> 32
        u64 n[32];
        #pragma unroll
        for (int o = 0; o < 32; ++o) {
            u64 t = b1q[o];
            const u64x2* wrow = w1q + o * 16;
            #pragma unroll
            for (int iq = 0; iq < 16; ++iq) {
                u64x2 w = wrow[iq];
                t = fma2(w.x, a[2 * iq], t);
                t = fma2(w.y, a[2 * iq + 1], t);
            }
            n[o] = relu2(t);
        }

        // layer 2: 32 -> 32
        #pragma unroll
        for (int o = 0; o < 32; ++o) {
            u64 t = b2q[o];
            const u64x2* wrow = w2q + o * 16;
            #pragma unroll
            for (int iq = 0; iq < 16; ++iq) {
                u64x2 w = wrow[iq];
                t = fma2(w.x, n[2 * iq], t);
                t = fma2(w.y, n[2 * iq + 1], t);
            }
            a[o] = relu2(t);
        }

        // layer 3: 32 -> 1
        u64 t = b3q[0];
        #pragma unroll
        for (int iq = 0; iq < 16; ++iq) {
            u64x2 w = w3q[iq];
            t = fma2(w.x, a[2 * iq], t);
            t = fma2(w.y, a[2 * iq + 1], t);
        }

        float lo, hi; unpack2(t, lo, hi);
        const int p = tid + kp * 128;
        out[(2 * p) * (S * D) + base]     = lo;
        out[(2 * p + 1) * (S * D) + base] = hi;
    }
}

// ---------------- launch ----------------
extern "C" void kernel_launch(void* const* d_in, const int* in_sizes, int n_in,
                              void* d_out, int out_size)
{
    const float* x  = (const float*)d_in[0];
    const float* z  = (const float*)d_in[1];
    const float* W0 = (const float*)d_in[2];
    const float* b0 = (const float*)d_in[3];
    const float* W1 = (const float*)d_in[4];
    const float* b1 = (const float*)d_in[5];
    const float* W2 = (const float*)d_in[6];
    const float* b2 = (const float*)d_in[7];
    const float* W3 = (const float*)d_in[8];
    const float* b3 = (const float*)d_in[9];

    float* out = (float*)d_out;
    float* adj = out + OUT_ELEMS;   // tuple output: (out, z_adj) concatenated

    zadj_kernel<<<S, 512, 3 * 4096 * sizeof(float)>>>(z, adj);
    xpack_kernel<<<(BSZ * D) / 256, 256>>>(x);

    cudaFuncSetAttribute(mlp_kernel, cudaFuncAttributeMaxDynamicSharedMemorySize, SMEM_BYTES);
    dim3 grid(D, S);   // (c, s)
    mlp_kernel<<<grid, 128, SMEM_BYTES>>>(adj,
                                          W0, b0, W1, b1, W2, b2, W3, b3,
                                          out);
}

// round 13
// speedup vs baseline: 2.9197x; 2.9197x over previous
#include <cuda_runtime.h>
#include <cuda_bf16.h>
#include <cstdint>

// Problem constants
#define D        64
#define S        64
#define BSZ      512
#define LTW      2016          // d*(d-1)/2
#define ZROW     6112          // lt + d*d
#define OUT_ELEMS (BSZ * S * D) // 2097152, z_adj follows at this offset

// ---------------- helpers ----------------
__device__ __forceinline__ uint32_t pack_h(unsigned short lo, unsigned short hi) {
    return (uint32_t)lo | ((uint32_t)hi << 16);
}
__device__ __forceinline__ void bsplit(float v, unsigned short& h, unsigned short& l) {
    __nv_bfloat16 bh = __float2bfloat16(v);
    float r = v - __bfloat162float(bh);
    __nv_bfloat16 bl = __float2bfloat16(r);
    h = *(unsigned short*)&bh;
    l = *(unsigned short*)&bl;
}

// mma.sync m16n8k16 row.col bf16 -> f32 accumulate (in-place on d)
__device__ __forceinline__ void mma16816(float* d, const uint32_t* a, uint32_t b0, uint32_t b1) {
    asm volatile(
        "mma.sync.aligned.m16n8k16.row.col.f32.bf16.bf16.f32 "
        "{%0,%1,%2,%3}, {%4,%5,%6,%7}, {%8,%9}, {%0,%1,%2,%3};"
        : "+f"(d[0]), "+f"(d[1]), "+f"(d[2]), "+f"(d[3])
        : "r"(a[0]), "r"(a[1]), "r"(a[2]), "r"(a[3]), "r"(b0), "r"(b1));
}

// x fragments: [w][mt][kt][lane][8 words]   words: a0h,a1h,a2h,a3h, a0l,a1l,a2l,a3l
__device__ uint32_t xfrag[4 * 8 * 4 * 32 * 8];

// ---------------- Kernel A: z_adj[s] = z_p^T @ z_lt @ z_p ----------------
__global__ void zadj_kernel(const float* __restrict__ z, float* __restrict__ adj_out) {
    extern __shared__ float sm[];
    float* lt  = sm;
    float* p   = sm + 4096;
    float* tmp = sm + 8192;
    const int s   = blockIdx.x;
    const int tid = threadIdx.x;
    const int nt  = blockDim.x;
    const float* zs = z + s * ZROW;

    for (int e = tid; e < 4096; e += nt) { lt[e] = 0.0f; p[e] = zs[LTW + e]; }
    __syncthreads();

    for (int k = tid; k < LTW; k += nt) {
        int i = (int)((sqrtf(8.0f * (float)k + 1.0f) + 1.0f) * 0.5f);
        while (i * (i - 1) / 2 > k)  --i;
        while ((i + 1) * i / 2 <= k) ++i;
        int j = k - i * (i - 1) / 2;
        lt[i * 64 + j] = zs[k];
    }
    __syncthreads();

    for (int e = tid; e < 4096; e += nt) {
        int r = e >> 6, j = e & 63;
        float acc = 0.0f;
        for (int t = 0; t < r; ++t) acc += lt[r * 64 + t] * p[t * 64 + j];
        tmp[e] = acc;
    }
    __syncthreads();

    for (int e = tid; e < 4096; e += nt) {
        int i = e >> 6, j = e & 63;
        float acc = 0.0f;
        #pragma unroll 8
        for (int r = 0; r < 64; ++r) acc += p[r * 64 + i] * tmp[r * 64 + j];
        adj_out[s * 4096 + e] = acc;
    }
}

// ---------------- Kernel A2: build xfrag (hi/lo split, fragment layout) ----------------
__global__ void xprep_kernel(const float* __restrict__ x) {
    int id = blockIdx.x * 256 + threadIdx.x;   // 0..16383 : (w,mt,kt,t,ai)
    int ai = id & 3;
    int t  = (id >> 2) & 31;
    int kt = (id >> 7) & 3;
    int mt = (id >> 9) & 7;
    int w  = id >> 12;
    int q  = t & 3;
    int r  = (t >> 2) + (ai & 1) * 8;
    int brow = w * 128 + mt * 16 + r;
    int cb = kt * 16 + 2 * q + ((ai >> 1) ? 8 : 0);
    float v0 = x[brow * 64 + cb];
    float v1 = x[brow * 64 + cb + 1];
    unsigned short h0, l0, h1, l1;
    bsplit(v0, h0, l0);
    bsplit(v1, h1, l1);
    uint32_t base = (uint32_t)((((w * 8 + mt) * 4 + kt) * 32 + t) * 8);
    xfrag[base + ai]     = pack_h(h0, h1);
    xfrag[base + 4 + ai] = pack_h(l0, l1);
}

// ---------------- Kernel B: HMMA fused MLP ----------------
// Grid (c, s) = 64x64; 128 threads = 4 warps, warp w handles batches [w*128, w*128+128).
// Per-lane weight fragments pre-cooked in shared: uint4 {b0h, b0l, b1h, b1l}.
__global__ void __launch_bounds__(128, 4) mlp_mma_kernel(
    const float* __restrict__ adj,
    const float* __restrict__ W0, const float* __restrict__ b0,
    const float* __restrict__ W1, const float* __restrict__ b1,
    const float* __restrict__ W2, const float* __restrict__ b2,
    const float* __restrict__ W3, const float* __restrict__ b3,
    float* __restrict__ out)
{
    __shared__ __align__(16) uint4 bf0[4][4][32];   // [nt][kt][lane]  8KB
    __shared__ __align__(16) uint4 bf1[4][2][32];   // 4KB
    __shared__ __align__(16) uint4 bf2[4][2][32];   // 4KB
    __shared__ float bias0[32], bias1[32], bias2[32], w3s[32], b3s;
    __shared__ float zcs[64];

    const int c = blockIdx.x, s = blockIdx.y;
    const int tid = threadIdx.x;
    const int wid = tid >> 5, lane = tid & 31;
    const int q = lane & 3, nrow = lane >> 2;

    // ---- stage scalars ----
    if (tid < 64) zcs[tid] = adj[s * 4096 + tid * 64 + c];
    if (tid < 32) {
        bias0[tid] = b0[c * 32 + tid];
        bias1[tid] = b1[c * 32 + tid];
        bias2[tid] = b2[c * 32 + tid];
        w3s[tid]   = W3[c * 32 + tid];
    }
    if (tid == 0) b3s = b3[c];
    __syncthreads();

    // ---- stage layer-0 weight fragments (W0 * zc, hi/lo split) ----
    // item e in [0,512): nt = e>>7, kt = (e>>5)&3, t = e&31
    #pragma unroll
    for (int it = 0; it < 4; ++it) {
        int e = tid + it * 128;
        int fnt = e >> 7, fkt = (e >> 5) & 3, ft = e & 31;
        int fq = ft & 3;
        int n = fnt * 8 + (ft >> 2);
        int k0 = fkt * 16 + 2 * fq;
        const float* wr = W0 + c * 2048 + n * 64;
        float v00 = wr[k0]     * zcs[k0];
        float v01 = wr[k0 + 1] * zcs[k0 + 1];
        float v10 = wr[k0 + 8] * zcs[k0 + 8];
        float v11 = wr[k0 + 9] * zcs[k0 + 9];
        unsigned short h, l, h2, l2;
        uint4 r;
        bsplit(v00, h, l); bsplit(v01, h2, l2);
        r.x = pack_h(h, h2); r.y = pack_h(l, l2);
        bsplit(v10, h, l); bsplit(v11, h2, l2);
        r.z = pack_h(h, h2); r.w = pack_h(l, l2);
        bf0[fnt][fkt][ft] = r;
    }
    // ---- stage layer-1/2 fragments: items e in [0,256) each ----
    #pragma unroll
    for (int it = 0; it < 2; ++it) {
        int e = tid + it * 128;
        int fnt = e >> 6, fkt = (e >> 5) & 1, ft = e & 31;
        int fq = ft & 3;
        int n = fnt * 8 + (ft >> 2);
        int k0 = fkt * 16 + 2 * fq;
        {
            const float* wr = W1 + c * 1024 + n * 32;
            unsigned short h, l, h2, l2;
            uint4 r;
            bsplit(wr[k0], h, l); bsplit(wr[k0 + 1], h2, l2);
            r.x = pack_h(h, h2); r.y = pack_h(l, l2);
            bsplit(wr[k0 + 8], h, l); bsplit(wr[k0 + 9], h2, l2);
            r.z = pack_h(h, h2); r.w = pack_h(l, l2);
            bf1[fnt][fkt][ft] = r;
        }
        {
            const float* wr = W2 + c * 1024 + n * 32;
            unsigned short h, l, h2, l2;
            uint4 r;
            bsplit(wr[k0], h, l); bsplit(wr[k0 + 1], h2, l2);
            r.x = pack_h(h, h2); r.y = pack_h(l, l2);
            bsplit(wr[k0 + 8], h, l); bsplit(wr[k0 + 9], h2, l2);
            r.z = pack_h(h, h2); r.w = pack_h(l, l2);
            bf2[fnt][fkt][ft] = r;
        }
    }
    __syncthreads();

    // per-thread bias pairs (col = nt*8 + 2q + {0,1})
    float bi0[4][2], bi1[4][2], bi2[4][2], w3v[4][2];
    #pragma unroll
    for (int nt = 0; nt < 4; ++nt) {
        int col = nt * 8 + 2 * q;
        bi0[nt][0] = bias0[col]; bi0[nt][1] = bias0[col + 1];
        bi1[nt][0] = bias1[col]; bi1[nt][1] = bias1[col + 1];
        bi2[nt][0] = bias2[col]; bi2[nt][1] = bias2[col + 1];
        w3v[nt][0] = w3s[col];   w3v[nt][1] = w3s[col + 1];
    }

    const int base_out = s * 64 + c;

    #pragma unroll 1
    for (int mt = 0; mt < 8; ++mt) {
        // ---- load A0 fragments (hi & lo) ----
        uint32_t aH[4][4], aL[4][4];
        #pragma unroll
        for (int kt = 0; kt < 4; ++kt) {
            const uint4* src = (const uint4*)(xfrag + (((wid * 8 + mt) * 4 + kt) * 32 + lane) * 8);
            uint4 vh = src[0], vl = src[1];
            aH[kt][0] = vh.x; aH[kt][1] = vh.y; aH[kt][2] = vh.z; aH[kt][3] = vh.w;
            aL[kt][0] = vl.x; aL[kt][1] = vl.y; aL[kt][2] = vl.z; aL[kt][3] = vl.w;
        }

        // ---- layer 0: K=64, 4 nt, 12 mma each ----
        uint32_t nAh[2][4], nAl[2][4];
        #pragma unroll
        for (int nt = 0; nt < 4; ++nt) {
            float dd[4] = { bi0[nt][0], bi0[nt][1], bi0[nt][0], bi0[nt][1] };
            #pragma unroll
            for (int kt = 0; kt < 4; ++kt) {
                uint4 B = bf0[nt][kt][lane];
                mma16816(dd, aH[kt], B.x, B.z);   // hi*hi
                mma16816(dd, aH[kt], B.y, B.w);   // hi*lo
                mma16816(dd, aL[kt], B.x, B.z);   // lo*hi
            }
            // relu + split -> next-layer A fragments (in-register)
            unsigned short h0, l0, h1, l1, h2, l2, h3, l3;
            bsplit(fmaxf(dd[0], 0.0f), h0, l0);
            bsplit(fmaxf(dd[1], 0.0f), h1, l1);
            bsplit(fmaxf(dd[2], 0.0f), h2, l2);
            bsplit(fmaxf(dd[3], 0.0f), h3, l3);
            int kt2 = nt >> 1, half = (nt & 1) * 2;
            nAh[kt2][half]     = pack_h(h0, h1);
            nAh[kt2][half + 1] = pack_h(h2, h3);
            nAl[kt2][half]     = pack_h(l0, l1);
            nAl[kt2][half + 1] = pack_h(l2, l3);
        }

        // ---- layer 1: K=32 ----
        uint32_t mAh[2][4], mAl[2][4];
        #pragma unroll
        for (int nt = 0; nt < 4; ++nt) {
            float dd[4] = { bi1[nt][0], bi1[nt][1], bi1[nt][0], bi1[nt][1] };
            #pragma unroll
            for (int kt = 0; kt < 2; ++kt) {
                uint4 B = bf1[nt][kt][lane];
                mma16816(dd, nAh[kt], B.x, B.z);
                mma16816(dd, nAh[kt], B.y, B.w);
                mma16816(dd, nAl[kt], B.x, B.z);
            }
            unsigned short h0, l0, h1, l1, h2, l2, h3, l3;
            bsplit(fmaxf(dd[0], 0.0f), h0, l0);
            bsplit(fmaxf(dd[1], 0.0f), h1, l1);
            bsplit(fmaxf(dd[2], 0.0f), h2, l2);
            bsplit(fmaxf(dd[3], 0.0f), h3, l3);
            int kt2 = nt >> 1, half = (nt & 1) * 2;
            mAh[kt2][half]     = pack_h(h0, h1);
            mAh[kt2][half + 1] = pack_h(h2, h3);
            mAl[kt2][half]     = pack_h(l0, l1);
            mAl[kt2][half + 1] = pack_h(l2, l3);
        }

        // ---- layer 2 + layer 3 fused ----
        float s0 = 0.0f, s8 = 0.0f;
        #pragma unroll
        for (int nt = 0; nt < 4; ++nt) {
            float dd[4] = { bi2[nt][0], bi2[nt][1], bi2[nt][0], bi2[nt][1] };
            #pragma unroll
            for (int kt = 0; kt < 2; ++kt) {
                uint4 B = bf2[nt][kt][lane];
                mma16816(dd, mAh[kt], B.x, B.z);
                mma16816(dd, mAh[kt], B.y, B.w);
                mma16816(dd, mAl[kt], B.x, B.z);
            }
            s0 = fmaf(w3v[nt][0], fmaxf(dd[0], 0.0f), s0);
            s0 = fmaf(w3v[nt][1], fmaxf(dd[1], 0.0f), s0);
            s8 = fmaf(w3v[nt][0], fmaxf(dd[2], 0.0f), s8);
            s8 = fmaf(w3v[nt][1], fmaxf(dd[3], 0.0f), s8);
        }
        // quad butterfly reduce over q (cols)
        s0 += __shfl_xor_sync(0xFFFFFFFF, s0, 1);
        s0 += __shfl_xor_sync(0xFFFFFFFF, s0, 2);
        s8 += __shfl_xor_sync(0xFFFFFFFF, s8, 1);
        s8 += __shfl_xor_sync(0xFFFFFFFF, s8, 2);

        if (q == 0) {
            int b = wid * 128 + mt * 16 + nrow;
            out[b * (S * D) + base_out]       = s0 + b3s;
            out[(b + 8) * (S * D) + base_out] = s8 + b3s;
        }
    }
}

// ---------------- launch ----------------
extern "C" void kernel_launch(void* const* d_in, const int* in_sizes, int n_in,
                              void* d_out, int out_size)
{
    const float* x  = (const float*)d_in[0];
    const float* z  = (const float*)d_in[1];
    const float* W0 = (const float*)d_in[2];
    const float* b0 = (const float*)d_in[3];
    const float* W1 = (const float*)d_in[4];
    const float* b1 = (const float*)d_in[5];
    const float* W2 = (const float*)d_in[6];
    const float* b2 = (const float*)d_in[7];
    const float* W3 = (const float*)d_in[8];
    const float* b3 = (const float*)d_in[9];

    float* out  = (float*)d_out;
    float* adjp = out + OUT_ELEMS;  // tuple output: (out, z_adj)

    zadj_kernel<<<S, 512, 3 * 4096 * sizeof(float)>>>(z, adjp);
    xprep_kernel<<<64, 256>>>(x);

    dim3 grid(D, S);   // (c, s)
    mlp_mma_kernel<<<grid, 128>>>(adjp,
                                  W0, b0, W1, b1, W2, b2, W3, b3,
                                  out);
}

// round 14
// speedup vs baseline: 2.9244x; 1.0016x over previous
#include <cuda_runtime.h>
#include <cuda_bf16.h>
#include <cstdint>

// Problem constants
#define D        64
#define S        64
#define BSZ      512
#define LTW      2016          // d*(d-1)/2
#define ZROW     6112          // lt + d*d
#define OUT_ELEMS (BSZ * S * D) // 2097152, z_adj follows at this offset

// ---------------- helpers ----------------
__device__ __forceinline__ uint32_t pack_h(unsigned short lo, unsigned short hi) {
    return (uint32_t)lo | ((uint32_t)hi << 16);
}
__device__ __forceinline__ void bsplit(float v, unsigned short& h, unsigned short& l) {
    __nv_bfloat16 bh = __float2bfloat16(v);
    float r = v - __bfloat162float(bh);
    __nv_bfloat16 bl = __float2bfloat16(r);
    h = *(unsigned short*)&bh;
    l = *(unsigned short*)&bl;
}

// mma.sync m16n8k16 row.col bf16 -> f32 accumulate (in-place on d)
__device__ __forceinline__ void mma16816(float* d, const uint32_t* a, uint32_t b0, uint32_t b1) {
    asm volatile(
        "mma.sync.aligned.m16n8k16.row.col.f32.bf16.bf16.f32 "
        "{%0,%1,%2,%3}, {%4,%5,%6,%7}, {%8,%9}, {%0,%1,%2,%3};"
        : "+f"(d[0]), "+f"(d[1]), "+f"(d[2]), "+f"(d[3])
        : "r"(a[0]), "r"(a[1]), "r"(a[2]), "r"(a[3]), "r"(b0), "r"(b1));
}

// x fragments: [w][mt][kt][lane][8 words]   words: a0h,a1h,a2h,a3h, a0l,a1l,a2l,a3l
__device__ uint32_t xfrag[4 * 8 * 4 * 32 * 8];

// ---------------- Kernel A: z_adj[s] = z_p^T @ z_lt @ z_p ----------------
__global__ void zadj_kernel(const float* __restrict__ z, float* __restrict__ adj_out) {
    extern __shared__ float sm[];
    float* lt  = sm;
    float* p   = sm + 4096;
    float* tmp = sm + 8192;
    const int s   = blockIdx.x;
    const int tid = threadIdx.x;
    const int nt  = blockDim.x;
    const float* zs = z + s * ZROW;

    for (int e = tid; e < 4096; e += nt) { lt[e] = 0.0f; p[e] = zs[LTW + e]; }
    __syncthreads();

    for (int k = tid; k < LTW; k += nt) {
        int i = (int)((sqrtf(8.0f * (float)k + 1.0f) + 1.0f) * 0.5f);
        while (i * (i - 1) / 2 > k)  --i;
        while ((i + 1) * i / 2 <= k) ++i;
        int j = k - i * (i - 1) / 2;
        lt[i * 64 + j] = zs[k];
    }
    __syncthreads();

    for (int e = tid; e < 4096; e += nt) {
        int r = e >> 6, j = e & 63;
        float acc = 0.0f;
        for (int t = 0; t < r; ++t) acc += lt[r * 64 + t] * p[t * 64 + j];
        tmp[e] = acc;
    }
    __syncthreads();

    for (int e = tid; e < 4096; e += nt) {
        int i = e >> 6, j = e & 63;
        float acc = 0.0f;
        #pragma unroll 8
        for (int r = 0; r < 64; ++r) acc += p[r * 64 + i] * tmp[r * 64 + j];
        adj_out[s * 4096 + e] = acc;
    }
}

// ---------------- Kernel A2: build xfrag (hi/lo split, fragment layout) ----------------
__global__ void xprep_kernel(const float* __restrict__ x) {
    int id = blockIdx.x * 256 + threadIdx.x;   // 0..16383 : (w,mt,kt,t,ai)
    int ai = id & 3;
    int t  = (id >> 2) & 31;
    int kt = (id >> 7) & 3;
    int mt = (id >> 9) & 7;
    int w  = id >> 12;
    int q  = t & 3;
    int r  = (t >> 2) + (ai & 1) * 8;
    int brow = w * 128 + mt * 16 + r;
    int cb = kt * 16 + 2 * q + ((ai >> 1) ? 8 : 0);
    float v0 = x[brow * 64 + cb];
    float v1 = x[brow * 64 + cb + 1];
    unsigned short h0, l0, h1, l1;
    bsplit(v0, h0, l0);
    bsplit(v1, h1, l1);
    uint32_t base = (uint32_t)((((w * 8 + mt) * 4 + kt) * 32 + t) * 8);
    xfrag[base + ai]     = pack_h(h0, h1);
    xfrag[base + 4 + ai] = pack_h(l0, l1);
}

// ---------------- Kernel B: HMMA fused MLP ----------------
// Grid (c, s) = 64x64; 128 threads = 4 warps, warp w handles batches [w*128, w*128+128).
// Per-lane weight fragments pre-cooked in shared: uint4 {b0h, b0l, b1h, b1l}.
__global__ void __launch_bounds__(128, 4) mlp_mma_kernel(
    const float* __restrict__ adj,
    const float* __restrict__ W0, const float* __restrict__ b0,
    const float* __restrict__ W1, const float* __restrict__ b1,
    const float* __restrict__ W2, const float* __restrict__ b2,
    const float* __restrict__ W3, const float* __restrict__ b3,
    float* __restrict__ out)
{
    __shared__ __align__(16) uint4 bf0[4][4][32];   // [nt][kt][lane]  8KB
    __shared__ __align__(16) uint4 bf1[4][2][32];   // 4KB
    __shared__ __align__(16) uint4 bf2[4][2][32];   // 4KB
    __shared__ float bias0[32], bias1[32], bias2[32], w3s[32], b3s;
    __shared__ float zcs[64];

    const int c = blockIdx.x, s = blockIdx.y;
    const int tid = threadIdx.x;
    const int wid = tid >> 5, lane = tid & 31;
    const int q = lane & 3, nrow = lane >> 2;

    // ---- stage scalars ----
    if (tid < 64) zcs[tid] = adj[s * 4096 + tid * 64 + c];
    if (tid < 32) {
        bias0[tid] = b0[c * 32 + tid];
        bias1[tid] = b1[c * 32 + tid];
        bias2[tid] = b2[c * 32 + tid];
        w3s[tid]   = W3[c * 32 + tid];
    }
    if (tid == 0) b3s = b3[c];
    __syncthreads();

    // ---- stage layer-0 weight fragments (W0 * zc, hi/lo split) ----
    // item e in [0,512): nt = e>>7, kt = (e>>5)&3, t = e&31
    #pragma unroll
    for (int it = 0; it < 4; ++it) {
        int e = tid + it * 128;
        int fnt = e >> 7, fkt = (e >> 5) & 3, ft = e & 31;
        int fq = ft & 3;
        int n = fnt * 8 + (ft >> 2);
        int k0 = fkt * 16 + 2 * fq;
        const float* wr = W0 + c * 2048 + n * 64;
        float v00 = wr[k0]     * zcs[k0];
        float v01 = wr[k0 + 1] * zcs[k0 + 1];
        float v10 = wr[k0 + 8] * zcs[k0 + 8];
        float v11 = wr[k0 + 9] * zcs[k0 + 9];
        unsigned short h, l, h2, l2;
        uint4 r;
        bsplit(v00, h, l); bsplit(v01, h2, l2);
        r.x = pack_h(h, h2); r.y = pack_h(l, l2);
        bsplit(v10, h, l); bsplit(v11, h2, l2);
        r.z = pack_h(h, h2); r.w = pack_h(l, l2);
        bf0[fnt][fkt][ft] = r;
    }
    // ---- stage layer-1/2 fragments: items e in [0,256) each ----
    #pragma unroll
    for (int it = 0; it < 2; ++it) {
        int e = tid + it * 128;
        int fnt = e >> 6, fkt = (e >> 5) & 1, ft = e & 31;
        int fq = ft & 3;
        int n = fnt * 8 + (ft >> 2);
        int k0 = fkt * 16 + 2 * fq;
        {
            const float* wr = W1 + c * 1024 + n * 32;
            unsigned short h, l, h2, l2;
            uint4 r;
            bsplit(wr[k0], h, l); bsplit(wr[k0 + 1], h2, l2);
            r.x = pack_h(h, h2); r.y = pack_h(l, l2);
            bsplit(wr[k0 + 8], h, l); bsplit(wr[k0 + 9], h2, l2);
            r.z = pack_h(h, h2); r.w = pack_h(l, l2);
            bf1[fnt][fkt][ft] = r;
        }
        {
            const float* wr = W2 + c * 1024 + n * 32;
            unsigned short h, l, h2, l2;
            uint4 r;
            bsplit(wr[k0], h, l); bsplit(wr[k0 + 1], h2, l2);
            r.x = pack_h(h, h2); r.y = pack_h(l, l2);
            bsplit(wr[k0 + 8], h, l); bsplit(wr[k0 + 9], h2, l2);
            r.z = pack_h(h, h2); r.w = pack_h(l, l2);
            bf2[fnt][fkt][ft] = r;
        }
    }
    __syncthreads();

    // per-thread bias pairs (col = nt*8 + 2q + {0,1})
    float bi0[4][2], bi1[4][2], bi2[4][2], w3v[4][2];
    #pragma unroll
    for (int nt = 0; nt < 4; ++nt) {
        int col = nt * 8 + 2 * q;
        bi0[nt][0] = bias0[col]; bi0[nt][1] = bias0[col + 1];
        bi1[nt][0] = bias1[col]; bi1[nt][1] = bias1[col + 1];
        bi2[nt][0] = bias2[col]; bi2[nt][1] = bias2[col + 1];
        w3v[nt][0] = w3s[col];   w3v[nt][1] = w3s[col + 1];
    }

    const int base_out = s * 64 + c;

    #pragma unroll 1
    for (int mt = 0; mt < 8; ++mt) {
        // ---- load A0 fragments (hi & lo) ----
        uint32_t aH[4][4], aL[4][4];
        #pragma unroll
        for (int kt = 0; kt < 4; ++kt) {
            const uint4* src = (const uint4*)(xfrag + (((wid * 8 + mt) * 4 + kt) * 32 + lane) * 8);
            uint4 vh = src[0], vl = src[1];
            aH[kt][0] = vh.x; aH[kt][1] = vh.y; aH[kt][2] = vh.z; aH[kt][3] = vh.w;
            aL[kt][0] = vl.x; aL[kt][1] = vl.y; aL[kt][2] = vl.z; aL[kt][3] = vl.w;
        }

        // ---- layer 0: K=64, 4 nt, 12 mma each ----
        uint32_t nAh[2][4], nAl[2][4];
        #pragma unroll
        for (int nt = 0; nt < 4; ++nt) {
            float dd[4] = { bi0[nt][0], bi0[nt][1], bi0[nt][0], bi0[nt][1] };
            #pragma unroll
            for (int kt = 0; kt < 4; ++kt) {
                uint4 B = bf0[nt][kt][lane];
                mma16816(dd, aH[kt], B.x, B.z);   // hi*hi
                mma16816(dd, aH[kt], B.y, B.w);   // hi*lo
                mma16816(dd, aL[kt], B.x, B.z);   // lo*hi
            }
            // relu + split -> next-layer A fragments (in-register)
            unsigned short h0, l0, h1, l1, h2, l2, h3, l3;
            bsplit(fmaxf(dd[0], 0.0f), h0, l0);
            bsplit(fmaxf(dd[1], 0.0f), h1, l1);
            bsplit(fmaxf(dd[2], 0.0f), h2, l2);
            bsplit(fmaxf(dd[3], 0.0f), h3, l3);
            int kt2 = nt >> 1, half = (nt & 1) * 2;
            nAh[kt2][half]     = pack_h(h0, h1);
            nAh[kt2][half + 1] = pack_h(h2, h3);
            nAl[kt2][half]     = pack_h(l0, l1);
            nAl[kt2][half + 1] = pack_h(l2, l3);
        }

        // ---- layer 1: K=32 ----
        uint32_t mAh[2][4], mAl[2][4];
        #pragma unroll
        for (int nt = 0; nt < 4; ++nt) {
            float dd[4] = { bi1[nt][0], bi1[nt][1], bi1[nt][0], bi1[nt][1] };
            #pragma unroll
            for (int kt = 0; kt < 2; ++kt) {
                uint4 B = bf1[nt][kt][lane];
                mma16816(dd, nAh[kt], B.x, B.z);
                mma16816(dd, nAh[kt], B.y, B.w);
                mma16816(dd, nAl[kt], B.x, B.z);
            }
            unsigned short h0, l0, h1, l1, h2, l2, h3, l3;
            bsplit(fmaxf(dd[0], 0.0f), h0, l0);
            bsplit(fmaxf(dd[1], 0.0f), h1, l1);
            bsplit(fmaxf(dd[2], 0.0f), h2, l2);
            bsplit(fmaxf(dd[3], 0.0f), h3, l3);
            int kt2 = nt >> 1, half = (nt & 1) * 2;
            mAh[kt2][half]     = pack_h(h0, h1);
            mAh[kt2][half + 1] = pack_h(h2, h3);
            mAl[kt2][half]     = pack_h(l0, l1);
            mAl[kt2][half + 1] = pack_h(l2, l3);
        }

        // ---- layer 2 + layer 3 fused ----
        float s0 = 0.0f, s8 = 0.0f;
        #pragma unroll
        for (int nt = 0; nt < 4; ++nt) {
            float dd[4] = { bi2[nt][0], bi2[nt][1], bi2[nt][0], bi2[nt][1] };
            #pragma unroll
            for (int kt = 0; kt < 2; ++kt) {
                uint4 B = bf2[nt][kt][lane];
                mma16816(dd, mAh[kt], B.x, B.z);
                mma16816(dd, mAh[kt], B.y, B.w);
                mma16816(dd, mAl[kt], B.x, B.z);
            }
            s0 = fmaf(w3v[nt][0], fmaxf(dd[0], 0.0f), s0);
            s0 = fmaf(w3v[nt][1], fmaxf(dd[1], 0.0f), s0);
            s8 = fmaf(w3v[nt][0], fmaxf(dd[2], 0.0f), s8);
            s8 = fmaf(w3v[nt][1], fmaxf(dd[3], 0.0f), s8);
        }
        // quad butterfly reduce over q (cols)
        s0 += __shfl_xor_sync(0xFFFFFFFF, s0, 1);
        s0 += __shfl_xor_sync(0xFFFFFFFF, s0, 2);
        s8 += __shfl_xor_sync(0xFFFFFFFF, s8, 1);
        s8 += __shfl_xor_sync(0xFFFFFFFF, s8, 2);

        if (q == 0) {
            int b = wid * 128 + mt * 16 + nrow;
            out[b * (S * D) + base_out]       = s0 + b3s;
            out[(b + 8) * (S * D) + base_out] = s8 + b3s;
        }
    }
}

// ---------------- launch ----------------
extern "C" void kernel_launch(void* const* d_in, const int* in_sizes, int n_in,
                              void* d_out, int out_size)
{
    const float* x  = (const float*)d_in[0];
    const float* z  = (const float*)d_in[1];
    const float* W0 = (const float*)d_in[2];
    const float* b0 = (const float*)d_in[3];
    const float* W1 = (const float*)d_in[4];
    const float* b1 = (const float*)d_in[5];
    const float* W2 = (const float*)d_in[6];
    const float* b2 = (const float*)d_in[7];
    const float* W3 = (const float*)d_in[8];
    const float* b3 = (const float*)d_in[9];

    float* out  = (float*)d_out;
    float* adjp = out + OUT_ELEMS;  // tuple output: (out, z_adj)

    zadj_kernel<<<S, 512, 3 * 4096 * sizeof(float)>>>(z, adjp);
    xprep_kernel<<<64, 256>>>(x);

    dim3 grid(D, S);   // (c, s)
    mlp_mma_kernel<<<grid, 128>>>(adjp,
                                  W0, b0, W1, b1, W2, b2, W3, b3,
                                  out);
}